// round 3
// baseline (speedup 1.0000x reference)
#include <cuda_runtime.h>
#include <cstdint>
#include <cstddef>

// ============================================================================
// DenseEquivariantMatrix: out[b,fo,g] = sum_{fi,h} x[b,fi,h]*kernel[fo,fi,pt[h,g]] + bias[fo]
//  == GEMM  D[2048, 8192] = A[2048,8192] @ W^T,  W[n][k] expanded by gather.
//
// sm_100 (no 'a'): tcgen05 unavailable -> mma.sync.m16n8k8.tf32 warp GEMM.
// K order is permuted (identically for A and W) so each thread's mma fragments
// are 32B-contiguous in SMEM -> LDS.128, conflict-free with SW128 swizzle.
//
// R3: unchanged from R2 — R2 bench was an infra failure (container died before
// compile); re-benching the audited kernel.
// ============================================================================

#define MDIM 2048
#define NDIM 8192
#define KDIM 8192
#define BM 128
#define BN 256
#define BK 32
#define NITER (KDIM / BK)           // 256
#define NSTAGE 3
#define A_BYTES (BM * BK * 4)       // 16384
#define B_BYTES (BN * BK * 4)       // 32768
#define STAGE_BYTES (A_BYTES + B_BYTES)
#define SMEM_TOTAL (NSTAGE * STAGE_BYTES)   // 147456

// -------- scratch (allocation-free: __device__ globals) --------
__device__ float g_A[MDIM * KDIM];         // 64 MB, tf32-rounded x, K-permuted
__device__ float g_W[(size_t)NDIM * KDIM]; // 256 MB, expanded tf32 kernel, K-permuted
__device__ int   g_ptT[256 * 256];         // transposed product table

// -------- helpers --------
#define SWZ(o) ((o) ^ (((o) >> 3) & 0x70))   // SW128 swizzle, 16B granular

__device__ __forceinline__ uint32_t f2tf32(float f) {
    uint32_t r;
    asm("cvt.rna.tf32.f32 %0, %1;" : "=r"(r) : "f"(f));
    return r;
}

// K permutation within each 32-block: k = 8s + tig + 4e  ->  p = 8*tig + 2s + e
// so thread (tig) reads its 8 needed values (s=0..3, e=0,1) contiguously.
__device__ __forceinline__ int permk(int k) {
    int k5 = k & 31;
    int s = k5 >> 3, tig = k5 & 3, e = (k5 >> 2) & 1;
    return (k & ~31) | (tig * 8 + s * 2 + e);
}

__device__ __forceinline__ void mma_tf32(float* c, uint32_t a0, uint32_t a1,
                                         uint32_t a2, uint32_t a3,
                                         uint32_t b0, uint32_t b1) {
    asm volatile(
        "mma.sync.aligned.m16n8k8.row.col.f32.tf32.tf32.f32 "
        "{%0,%1,%2,%3}, {%4,%5,%6,%7}, {%8,%9}, {%0,%1,%2,%3};"
        : "+f"(c[0]), "+f"(c[1]), "+f"(c[2]), "+f"(c[3])
        : "r"(a0), "r"(a1), "r"(a2), "r"(a3), "r"(b0), "r"(b1));
}

__device__ __forceinline__ void cp16(void* s, const void* g) {
    uint32_t sa;
    asm("{ .reg .u64 t; cvta.to.shared.u64 t, %1; cvt.u32.u64 %0, t; }"
        : "=r"(sa) : "l"(s));
    asm volatile("cp.async.cg.shared.global [%0], [%1], 16;" :: "r"(sa), "l"(g));
}

// ============================================================================
// Prep kernels
// ============================================================================

// x (fp32) -> g_A (tf32-rounded, K-permuted within 32-blocks)
__global__ void convert_x_kernel(const float* __restrict__ x) {
    int i = blockIdx.x * blockDim.x + threadIdx.x;   // 2048*8192 elements
    int b = i >> 13, k = i & 8191;
    g_A[(size_t)b * KDIM + permk(k)] = __uint_as_float(f2tf32(x[i]));
}

__global__ void transpose_pt_kernel(const int* __restrict__ pt) {
    int g = blockIdx.x, t = threadIdx.x;
    g_ptT[g * 256 + t] = pt[t * 256 + g];
}

// W[fo*256+g][perm(fi*256+h)] = tf32(kernel[fo][fi][pt[h,g]])
__global__ void expand_w_kernel(const float* __restrict__ kern) {
    __shared__ float krow[256];
    const int t = threadIdx.x;                       // h index
    const int fo = blockIdx.x >> 5;
    const int fi = blockIdx.x & 31;
    const int tp = (t & ~31) | (permk(t) & 31);      // permuted h position
    krow[t] = __uint_as_float(f2tf32(kern[(size_t)blockIdx.x * 256 + t]));
    __syncthreads();
    float* wb = g_W + (size_t)fo * 256 * KDIM + (size_t)fi * 256;
    #pragma unroll 4
    for (int g = 0; g < 256; ++g) {
        int s = g_ptT[g * 256 + t];                  // coalesced read
        wb[(size_t)g * KDIM + tp] = krow[s];         // coalesced write (perm within 128B)
    }
}

// ============================================================================
// GEMM: grid (16 m-tiles, 32 n-tiles), 256 threads, 1 CTA/SM
// warps 2x4, warp tile 64x64, mma.m16n8k8.tf32: 4 mt x 8 nt per warp
// ============================================================================
__global__ void __launch_bounds__(256, 1)
gemm_tf32(const float* __restrict__ bias, float* __restrict__ out) {
    extern __shared__ char smem[];
    const int tid  = threadIdx.x;
    const int wid  = tid >> 5;
    const int lane = tid & 31;
    const int g    = lane >> 2;        // group id (row within 8)
    const int tig  = lane & 3;         // thread in group
    const int wm   = wid >> 2;         // warp m (0..1)
    const int wn   = wid & 3;          // warp n (0..3)
    const int m0 = blockIdx.x * BM;
    const int n0 = blockIdx.y * BN;

    const float* Ab = g_A + (size_t)m0 * KDIM;
    const float* Bb = g_W + (size_t)n0 * KDIM;

    float acc[4][8][4];
    #pragma unroll
    for (int mt = 0; mt < 4; ++mt)
        #pragma unroll
        for (int nt = 0; nt < 8; ++nt)
            #pragma unroll
            for (int q = 0; q < 4; ++q) acc[mt][nt][q] = 0.f;

    // per-stage cp.async: A = 4 x 16B/thread, B = 8 x 16B/thread
    auto load_stage = [&](int s, int kiter) {
        const int k0 = kiter * BK;
        char* ta = smem + s * STAGE_BYTES;
        char* tb = ta + A_BYTES;
        #pragma unroll
        for (int i = 0; i < 4; ++i) {
            int idx = tid + (i << 8);
            int r = idx >> 3, c = idx & 7;
            cp16(ta + SWZ(r * 128 + c * 16), Ab + (size_t)r * KDIM + k0 + c * 4);
        }
        #pragma unroll
        for (int i = 0; i < 8; ++i) {
            int idx = tid + (i << 8);
            int r = idx >> 3, c = idx & 7;
            cp16(tb + SWZ(r * 128 + c * 16), Bb + (size_t)r * KDIM + k0 + c * 4);
        }
    };

    // prologue: stages 0,1
    load_stage(0, 0);
    asm volatile("cp.async.commit_group;" ::: "memory");
    load_stage(1, 1);
    asm volatile("cp.async.commit_group;" ::: "memory");

    // frag base offsets (byte offsets within stage, before swizzle)
    const int aRow0 = wm * 64 + g;            // + mt*16 (+8 for hi)
    const int bRow0 = wn * 64 + g;            // + nt*8
    const int fcol  = tig * 32;               // + h*16

    #pragma unroll 1
    for (int it = 0; it < NITER; ++it) {
        asm volatile("cp.async.wait_group 1;" ::: "memory");
        __syncthreads();

        const int ld = it + 2;
        if (ld < NITER) load_stage(ld % NSTAGE, ld);
        asm volatile("cp.async.commit_group;" ::: "memory");

        char* ta = smem + (it % NSTAGE) * STAGE_BYTES;
        char* tb = ta + A_BYTES;

        #pragma unroll
        for (int h = 0; h < 2; ++h) {          // two kstep-pairs per BK=32
            float4 af[4][2];
            float4 bf[8];
            #pragma unroll
            for (int mt = 0; mt < 4; ++mt) {
                int r = aRow0 + mt * 16;
                af[mt][0] = *(const float4*)(ta + SWZ(r * 128 + fcol + h * 16));
                af[mt][1] = *(const float4*)(ta + SWZ((r + 8) * 128 + fcol + h * 16));
            }
            #pragma unroll
            for (int nt = 0; nt < 8; ++nt) {
                int r = bRow0 + nt * 8;
                bf[nt] = *(const float4*)(tb + SWZ(r * 128 + fcol + h * 16));
            }
            // kstep 2h: components .x (e=0) / .y (e=1)
            #pragma unroll
            for (int mt = 0; mt < 4; ++mt) {
                uint32_t a0 = __float_as_uint(af[mt][0].x);
                uint32_t a1 = __float_as_uint(af[mt][1].x);
                uint32_t a2 = __float_as_uint(af[mt][0].y);
                uint32_t a3 = __float_as_uint(af[mt][1].y);
                #pragma unroll
                for (int nt = 0; nt < 8; ++nt)
                    mma_tf32(acc[mt][nt], a0, a1, a2, a3,
                             __float_as_uint(bf[nt].x), __float_as_uint(bf[nt].y));
            }
            // kstep 2h+1: components .z / .w
            #pragma unroll
            for (int mt = 0; mt < 4; ++mt) {
                uint32_t a0 = __float_as_uint(af[mt][0].z);
                uint32_t a1 = __float_as_uint(af[mt][1].z);
                uint32_t a2 = __float_as_uint(af[mt][0].w);
                uint32_t a3 = __float_as_uint(af[mt][1].w);
                #pragma unroll
                for (int nt = 0; nt < 8; ++nt)
                    mma_tf32(acc[mt][nt], a0, a1, a2, a3,
                             __float_as_uint(bf[nt].z), __float_as_uint(bf[nt].w));
            }
        }
    }

    // epilogue: bias + store. One f_out per CTA column (BN == 256).
    const float bv = bias[blockIdx.y];
    #pragma unroll
    for (int mt = 0; mt < 4; ++mt) {
        const int r0 = m0 + wm * 64 + mt * 16 + g;
        #pragma unroll
        for (int nt = 0; nt < 8; ++nt) {
            const int c = n0 + wn * 64 + nt * 8 + tig * 2;
            float2 v0 = { acc[mt][nt][0] + bv, acc[mt][nt][1] + bv };
            float2 v1 = { acc[mt][nt][2] + bv, acc[mt][nt][3] + bv };
            *(float2*)(out + (size_t)r0 * NDIM + c)       = v0;
            *(float2*)(out + (size_t)(r0 + 8) * NDIM + c) = v1;
        }
    }
}

// ============================================================================
// Launch
// ============================================================================
extern "C" void kernel_launch(void* const* d_in, const int* in_sizes, int n_in,
                              void* d_out, int out_size) {
    const float* x    = (const float*)d_in[0];   // (2048, 32, 256)
    const float* kern = (const float*)d_in[1];   // (32, 32, 256)
    const float* bias = (const float*)d_in[2];   // (32,)
    const int*   pt   = (const int*)d_in[3];     // (256, 256)
    float* out = (float*)d_out;                  // (2048, 32, 256)

    cudaFuncSetAttribute(gemm_tf32, cudaFuncAttributeMaxDynamicSharedMemorySize,
                         SMEM_TOTAL);

    convert_x_kernel<<<MDIM * KDIM / 256, 256>>>(x);
    transpose_pt_kernel<<<256, 256>>>(pt);
    expand_w_kernel<<<1024, 256>>>(kern);
    gemm_tf32<<<dim3(MDIM / BM, NDIM / BN, 1), 256, SMEM_TOTAL>>>(bias, out);
}

// round 4
// speedup vs baseline: 1.0030x; 1.0030x over previous
#include <cuda_runtime.h>
#include <cstdint>
#include <cstddef>

// ============================================================================
// DenseEquivariantMatrix: out[b,fo,g] = sum_{fi,h} x[b,fi,h]*kernel[fo,fi,pt[h,g]] + bias[fo]
//  == GEMM  D[2048, 8192] = A[2048,8192] @ W^T,  W[n][k] expanded by gather.
//
// sm_100 (no 'a'): mma.sync.m16n8k8.tf32 warp GEMM (fallback HMMA, rt~8/SMSP).
// R4: 512 threads / 16 warps, warp tile 64x32 (acc 64 regs) -> 4 warps/SMSP
//     for load/mma phase overlap. R3 (8 warps, 253 regs) ran tensor=51%.
// K order is permuted (identically for A and W) so each thread's mma fragments
// are 32B-contiguous in SMEM -> LDS.128, conflict-free with SW128 swizzle.
// ============================================================================

#define MDIM 2048
#define NDIM 8192
#define KDIM 8192
#define BM 128
#define BN 256
#define BK 32
#define NITER (KDIM / BK)           // 256
#define NSTAGE 3
#define A_BYTES (BM * BK * 4)       // 16384
#define B_BYTES (BN * BK * 4)       // 32768
#define STAGE_BYTES (A_BYTES + B_BYTES)
#define SMEM_TOTAL (NSTAGE * STAGE_BYTES)   // 147456

// -------- scratch (allocation-free: __device__ globals) --------
__device__ float g_A[MDIM * KDIM];         // 64 MB, tf32-rounded x, K-permuted
__device__ float g_W[(size_t)NDIM * KDIM]; // 256 MB, expanded tf32 kernel, K-permuted
__device__ int   g_ptT[256 * 256];         // transposed product table

// -------- helpers --------
#define SWZ(o) ((o) ^ (((o) >> 3) & 0x70))   // SW128 swizzle, 16B granular

__device__ __forceinline__ uint32_t f2tf32(float f) {
    uint32_t r;
    asm("cvt.rna.tf32.f32 %0, %1;" : "=r"(r) : "f"(f));
    return r;
}

// K permutation within each 32-block: k = 8s + tig + 4e  ->  p = 8*tig + 2s + e
__device__ __forceinline__ int permk(int k) {
    int k5 = k & 31;
    int s = k5 >> 3, tig = k5 & 3, e = (k5 >> 2) & 1;
    return (k & ~31) | (tig * 8 + s * 2 + e);
}

__device__ __forceinline__ void mma_tf32(float* c, uint32_t a0, uint32_t a1,
                                         uint32_t a2, uint32_t a3,
                                         uint32_t b0, uint32_t b1) {
    asm volatile(
        "mma.sync.aligned.m16n8k8.row.col.f32.tf32.tf32.f32 "
        "{%0,%1,%2,%3}, {%4,%5,%6,%7}, {%8,%9}, {%0,%1,%2,%3};"
        : "+f"(c[0]), "+f"(c[1]), "+f"(c[2]), "+f"(c[3])
        : "r"(a0), "r"(a1), "r"(a2), "r"(a3), "r"(b0), "r"(b1));
}

__device__ __forceinline__ void cp16(void* s, const void* g) {
    uint32_t sa;
    asm("{ .reg .u64 t; cvta.to.shared.u64 t, %1; cvt.u32.u64 %0, t; }"
        : "=r"(sa) : "l"(s));
    asm volatile("cp.async.cg.shared.global [%0], [%1], 16;" :: "r"(sa), "l"(g));
}

// ============================================================================
// Prep kernels
// ============================================================================

__global__ void convert_x_kernel(const float* __restrict__ x) {
    int i = blockIdx.x * blockDim.x + threadIdx.x;
    int b = i >> 13, k = i & 8191;
    g_A[(size_t)b * KDIM + permk(k)] = __uint_as_float(f2tf32(x[i]));
}

__global__ void transpose_pt_kernel(const int* __restrict__ pt) {
    int g = blockIdx.x, t = threadIdx.x;
    g_ptT[g * 256 + t] = pt[t * 256 + g];
}

__global__ void expand_w_kernel(const float* __restrict__ kern) {
    __shared__ float krow[256];
    const int t = threadIdx.x;
    const int fo = blockIdx.x >> 5;
    const int fi = blockIdx.x & 31;
    const int tp = (t & ~31) | (permk(t) & 31);
    krow[t] = __uint_as_float(f2tf32(kern[(size_t)blockIdx.x * 256 + t]));
    __syncthreads();
    float* wb = g_W + (size_t)fo * 256 * KDIM + (size_t)fi * 256;
    #pragma unroll 4
    for (int g = 0; g < 256; ++g) {
        int s = g_ptT[g * 256 + t];
        wb[(size_t)g * KDIM + tp] = krow[s];
    }
}

// ============================================================================
// GEMM: grid (16 m-tiles, 32 n-tiles), 512 threads, 1 CTA/SM
// warps 2x8, warp tile 64x32, mma.m16n8k8.tf32: 4 mt x 4 nt per warp
// ============================================================================
__global__ void __launch_bounds__(512, 1)
gemm_tf32(const float* __restrict__ bias, float* __restrict__ out) {
    extern __shared__ char smem[];
    const int tid  = threadIdx.x;
    const int wid  = tid >> 5;
    const int lane = tid & 31;
    const int g    = lane >> 2;        // group id (row within 8)
    const int tig  = lane & 3;         // thread in group
    const int wm   = wid >> 3;         // warp m (0..1) -> 64 rows
    const int wn   = wid & 7;          // warp n (0..7) -> 32 cols
    const int m0 = blockIdx.x * BM;
    const int n0 = blockIdx.y * BN;

    const float* Ab = g_A + (size_t)m0 * KDIM;
    const float* Bb = g_W + (size_t)n0 * KDIM;

    float acc[4][4][4];
    #pragma unroll
    for (int mt = 0; mt < 4; ++mt)
        #pragma unroll
        for (int nt = 0; nt < 4; ++nt)
            #pragma unroll
            for (int q = 0; q < 4; ++q) acc[mt][nt][q] = 0.f;

    // per-stage cp.async: A = 2 x 16B/thread, B = 4 x 16B/thread
    auto load_stage = [&](int s, int kiter) {
        const int k0 = kiter * BK;
        char* ta = smem + s * STAGE_BYTES;
        char* tb = ta + A_BYTES;
        #pragma unroll
        for (int i = 0; i < 2; ++i) {
            int idx = tid + (i << 9);
            int r = idx >> 3, c = idx & 7;
            cp16(ta + SWZ(r * 128 + c * 16), Ab + (size_t)r * KDIM + k0 + c * 4);
        }
        #pragma unroll
        for (int i = 0; i < 4; ++i) {
            int idx = tid + (i << 9);
            int r = idx >> 3, c = idx & 7;
            cp16(tb + SWZ(r * 128 + c * 16), Bb + (size_t)r * KDIM + k0 + c * 4);
        }
    };

    // prologue: stages 0,1
    load_stage(0, 0);
    asm volatile("cp.async.commit_group;" ::: "memory");
    load_stage(1, 1);
    asm volatile("cp.async.commit_group;" ::: "memory");

    const int aRow0 = wm * 64 + g;            // + mt*16 (+8 for hi)
    const int bRow0 = wn * 32 + g;            // + nt*8

    #pragma unroll 1
    for (int it = 0; it < NITER; ++it) {
        asm volatile("cp.async.wait_group 1;" ::: "memory");
        __syncthreads();

        const int ld = it + 2;
        if (ld < NITER) load_stage(ld % NSTAGE, ld);
        asm volatile("cp.async.commit_group;" ::: "memory");

        char* ta = smem + (it % NSTAGE) * STAGE_BYTES;
        char* tb = ta + A_BYTES;

        #pragma unroll
        for (int h = 0; h < 2; ++h) {          // two kstep-pairs per BK=32
            const int fcol = tig * 32 + h * 16;
            float4 bf[4];
            #pragma unroll
            for (int nt = 0; nt < 4; ++nt)
                bf[nt] = *(const float4*)(tb + SWZ((bRow0 + nt * 8) * 128 + fcol));
            #pragma unroll
            for (int mt = 0; mt < 4; ++mt) {
                const int r = aRow0 + mt * 16;
                float4 a0 = *(const float4*)(ta + SWZ(r * 128 + fcol));
                float4 a1 = *(const float4*)(ta + SWZ((r + 8) * 128 + fcol));
                // kstep 2h: components .x (e=0) / .y (e=1)
                #pragma unroll
                for (int nt = 0; nt < 4; ++nt)
                    mma_tf32(acc[mt][nt],
                             __float_as_uint(a0.x), __float_as_uint(a1.x),
                             __float_as_uint(a0.y), __float_as_uint(a1.y),
                             __float_as_uint(bf[nt].x), __float_as_uint(bf[nt].y));
                // kstep 2h+1: components .z / .w
                #pragma unroll
                for (int nt = 0; nt < 4; ++nt)
                    mma_tf32(acc[mt][nt],
                             __float_as_uint(a0.z), __float_as_uint(a1.z),
                             __float_as_uint(a0.w), __float_as_uint(a1.w),
                             __float_as_uint(bf[nt].z), __float_as_uint(bf[nt].w));
            }
        }
    }

    // epilogue: bias + store. One f_out per CTA column (BN == 256).
    const float bv = bias[blockIdx.y];
    #pragma unroll
    for (int mt = 0; mt < 4; ++mt) {
        const int r0 = m0 + wm * 64 + mt * 16 + g;
        #pragma unroll
        for (int nt = 0; nt < 4; ++nt) {
            const int c = n0 + wn * 32 + nt * 8 + tig * 2;
            float2 v0 = { acc[mt][nt][0] + bv, acc[mt][nt][1] + bv };
            float2 v1 = { acc[mt][nt][2] + bv, acc[mt][nt][3] + bv };
            *(float2*)(out + (size_t)r0 * NDIM + c)       = v0;
            *(float2*)(out + (size_t)(r0 + 8) * NDIM + c) = v1;
        }
    }
}

// ============================================================================
// Launch
// ============================================================================
extern "C" void kernel_launch(void* const* d_in, const int* in_sizes, int n_in,
                              void* d_out, int out_size) {
    const float* x    = (const float*)d_in[0];   // (2048, 32, 256)
    const float* kern = (const float*)d_in[1];   // (32, 32, 256)
    const float* bias = (const float*)d_in[2];   // (32,)
    const int*   pt   = (const int*)d_in[3];     // (256, 256)
    float* out = (float*)d_out;                  // (2048, 32, 256)

    cudaFuncSetAttribute(gemm_tf32, cudaFuncAttributeMaxDynamicSharedMemorySize,
                         SMEM_TOTAL);

    convert_x_kernel<<<MDIM * KDIM / 256, 256>>>(x);
    transpose_pt_kernel<<<256, 256>>>(pt);
    expand_w_kernel<<<1024, 256>>>(kern);
    gemm_tf32<<<dim3(MDIM / BM, NDIM / BN, 1), 512, SMEM_TOTAL>>>(bias, out);
}

// round 6
// speedup vs baseline: 1.9852x; 1.9792x over previous
#include <cuda_runtime.h>
#include <cuda_fp16.h>
#include <cstdint>
#include <cstddef>

// ============================================================================
// DenseEquivariantMatrix: out[b,fo,g] = sum_{fi,h} x[b,fi,h]*kernel[fo,fi,pt[h,g]] + bias[fo]
//  == GEMM  D[2048, 8192] = A[2048,8192] @ W^T,  W[n][k] expanded by gather.
//
// R5/R6: tf32 m16n8k8 -> fp16 m16n8k16 (same 10-bit mantissa, HALF the HMMA
//     instructions). R3/R4 proved we sit at the HMMA instruction ceiling
//     (tensor=51%, time invariant across occupancy/reg configs).
//     R5 bench was a broker infra failure (container died); re-benching the
//     audited kernel verbatim.
// K order permuted within 64-blocks (identically for A and W) so each thread's
// two-k16-block fragment set is one 16B LDS.128, conflict-free under SW128.
// ============================================================================

#define MDIM 2048
#define NDIM 8192
#define KDIM 8192
#define BM 128
#define BN 256
#define BK 64
#define NITER (KDIM / BK)           // 128
#define NSTAGE 3
#define A_BYTES (BM * BK * 2)       // 16384
#define B_BYTES (BN * BK * 2)       // 32768
#define STAGE_BYTES (A_BYTES + B_BYTES)
#define SMEM_TOTAL (NSTAGE * STAGE_BYTES)   // 147456

// -------- scratch (allocation-free: __device__ globals) --------
__device__ __half g_Ah[(size_t)MDIM * KDIM];   // 32 MB, fp16 x, K-permuted
__device__ __half g_Wh[(size_t)NDIM * KDIM];   // 128 MB, expanded fp16 kernel
__device__ int    g_ptT[256 * 256];            // transposed product table

// -------- helpers --------
#define SWZ(o) ((o) ^ (((o) >> 3) & 0x70))   // SW128 swizzle, 16B granular

// K permutation within each 64-block (fp16 m16n8k16 fragment order):
//   k = 32h + 16b + j,  decode: pair=j&1, tg=(j>>1)&3, hf=(j>>3)&1
//   p = tg*16 + h*8 + b*4 + hf*2 + pair
// => thread tig's fragment k-set {2t,2t+1,2t+8,2t+9} for both k16 blocks of a
//    given h is 16 contiguous bytes at fcol = tig*32 + h*16.
__device__ __forceinline__ int permk64(int k) {
    int k6 = k & 63;
    int h  = k6 >> 5;
    int b  = (k6 >> 4) & 1;
    int j  = k6 & 15;
    int pair = j & 1, tg = (j >> 1) & 3, hf = (j >> 3) & 1;
    return (k & ~63) | (tg * 16 + h * 8 + b * 4 + hf * 2 + pair);
}

__device__ __forceinline__ void mma_f16(float* c, uint32_t a0, uint32_t a1,
                                        uint32_t a2, uint32_t a3,
                                        uint32_t b0, uint32_t b1) {
    asm volatile(
        "mma.sync.aligned.m16n8k16.row.col.f32.f16.f16.f32 "
        "{%0,%1,%2,%3}, {%4,%5,%6,%7}, {%8,%9}, {%0,%1,%2,%3};"
        : "+f"(c[0]), "+f"(c[1]), "+f"(c[2]), "+f"(c[3])
        : "r"(a0), "r"(a1), "r"(a2), "r"(a3), "r"(b0), "r"(b1));
}

__device__ __forceinline__ void cp16(void* s, const void* g) {
    uint32_t sa;
    asm("{ .reg .u64 t; cvta.to.shared.u64 t, %1; cvt.u32.u64 %0, t; }"
        : "=r"(sa) : "l"(s));
    asm volatile("cp.async.cg.shared.global [%0], [%1], 16;" :: "r"(sa), "l"(g));
}

// ============================================================================
// Prep kernels
// ============================================================================

// x (fp32) -> g_Ah (fp16 RN, K-permuted). Even/odd k pairs stay adjacent under
// the perm (p even, p+1), so each thread converts one pair -> one half2 store;
// a warp's 64 k-span is one 128B line -> fully coalesced.
__global__ void convert_x_kernel(const float2* __restrict__ x2) {
    int i = blockIdx.x * blockDim.x + threadIdx.x;   // pair index, 2048*4096
    int b = i >> 12, j = i & 4095;
    int k = 2 * j;
    float2 v = x2[i];
    int p = permk64(k);                              // even -> half2-aligned
    *reinterpret_cast<__half2*>(&g_Ah[(size_t)b * KDIM + p]) =
        __floats2half2_rn(v.x, v.y);
}

__global__ void transpose_pt_kernel(const int* __restrict__ pt) {
    int g = blockIdx.x, t = threadIdx.x;
    g_ptT[g * 256 + t] = pt[t * 256 + g];
}

// W[fo*256+g][perm(fi*256+h)] = fp16(kernel[fo][fi][pt[h,g]])
// 256 threads: t>>7 picks even/odd g row, t&127 is the h-pair index.
__global__ void expand_w_kernel(const float* __restrict__ kern) {
    __shared__ float krow[256];
    const int t  = threadIdx.x;
    const int fo = blockIdx.x >> 5;
    const int fi = blockIdx.x & 31;
    krow[t] = kern[(size_t)blockIdx.x * 256 + t];
    __syncthreads();
    const int m  = t & 127;            // h-pair
    const int gh = t >> 7;             // 0/1
    const int p  = permk64(2 * m);     // even -> half2-aligned
    __half* wb = g_Wh + (size_t)fo * 256 * KDIM + (size_t)fi * 256;
    #pragma unroll 4
    for (int gi = 0; gi < 128; ++gi) {
        int g = gi * 2 + gh;
        int2 s = reinterpret_cast<const int2*>(g_ptT + g * 256)[m];
        *reinterpret_cast<__half2*>(wb + (size_t)g * KDIM + p) =
            __floats2half2_rn(krow[s.x], krow[s.y]);
    }
}

// ============================================================================
// GEMM: grid (16 m-tiles, 32 n-tiles), 512 threads, 1 CTA/SM
// warps 2x8, warp tile 64x32, mma.m16n8k16.f16: 4 mt x 4 nt x 4 k16 per iter
// ============================================================================
__global__ void __launch_bounds__(512, 1)
gemm_f16(const float* __restrict__ bias, float* __restrict__ out) {
    extern __shared__ char smem[];
    const int tid  = threadIdx.x;
    const int wid  = tid >> 5;
    const int lane = tid & 31;
    const int g    = lane >> 2;        // row within 8
    const int tig  = lane & 3;         // thread in group
    const int wm   = wid >> 3;         // warp m (0..1) -> 64 rows
    const int wn   = wid & 7;          // warp n (0..7) -> 32 cols
    const int m0 = blockIdx.x * BM;
    const int n0 = blockIdx.y * BN;

    const __half* Ab = g_Ah + (size_t)m0 * KDIM;
    const __half* Bb = g_Wh + (size_t)n0 * KDIM;

    float acc[4][4][4];
    #pragma unroll
    for (int mt = 0; mt < 4; ++mt)
        #pragma unroll
        for (int nt = 0; nt < 4; ++nt)
            #pragma unroll
            for (int q = 0; q < 4; ++q) acc[mt][nt][q] = 0.f;

    // per-stage cp.async: A = 2 x 16B/thread, B = 4 x 16B/thread (rows of 128B)
    auto load_stage = [&](int s, int kiter) {
        const int k0 = kiter * BK;
        char* ta = smem + s * STAGE_BYTES;
        char* tb = ta + A_BYTES;
        #pragma unroll
        for (int i = 0; i < 2; ++i) {
            int idx = tid + (i << 9);
            int r = idx >> 3, c = idx & 7;           // c: 16B chunk = 8 fp16
            cp16(ta + SWZ(r * 128 + c * 16), Ab + (size_t)r * KDIM + k0 + c * 8);
        }
        #pragma unroll
        for (int i = 0; i < 4; ++i) {
            int idx = tid + (i << 9);
            int r = idx >> 3, c = idx & 7;
            cp16(tb + SWZ(r * 128 + c * 16), Bb + (size_t)r * KDIM + k0 + c * 8);
        }
    };

    load_stage(0, 0);
    asm volatile("cp.async.commit_group;" ::: "memory");
    load_stage(1, 1);
    asm volatile("cp.async.commit_group;" ::: "memory");

    const int aRow0 = wm * 64 + g;
    const int bRow0 = wn * 32 + g;

    #pragma unroll 1
    for (int it = 0; it < NITER; ++it) {
        asm volatile("cp.async.wait_group 1;" ::: "memory");
        __syncthreads();

        const int ld = it + 2;
        if (ld < NITER) load_stage(ld % NSTAGE, ld);
        asm volatile("cp.async.commit_group;" ::: "memory");

        char* ta = smem + (it % NSTAGE) * STAGE_BYTES;
        char* tb = ta + A_BYTES;

        #pragma unroll
        for (int h = 0; h < 2; ++h) {              // two k16-block PAIRS per BK=64
            const int fcol = tig * 32 + h * 16;
            float4 bf[4];
            #pragma unroll
            for (int nt = 0; nt < 4; ++nt)
                bf[nt] = *(const float4*)(tb + SWZ((bRow0 + nt * 8) * 128 + fcol));
            #pragma unroll
            for (int mt = 0; mt < 4; ++mt) {
                const int r = aRow0 + mt * 16;
                float4 lo = *(const float4*)(ta + SWZ(r * 128 + fcol));
                float4 hi = *(const float4*)(ta + SWZ((r + 8) * 128 + fcol));
                // k16 block (2h):   lo.x=a0 hi.x=a1 lo.y=a2 hi.y=a3, bf.x=b0 bf.y=b1
                #pragma unroll
                for (int nt = 0; nt < 4; ++nt)
                    mma_f16(acc[mt][nt],
                            __float_as_uint(lo.x), __float_as_uint(hi.x),
                            __float_as_uint(lo.y), __float_as_uint(hi.y),
                            __float_as_uint(bf[nt].x), __float_as_uint(bf[nt].y));
                // k16 block (2h+1): .z/.w components
                #pragma unroll
                for (int nt = 0; nt < 4; ++nt)
                    mma_f16(acc[mt][nt],
                            __float_as_uint(lo.z), __float_as_uint(hi.z),
                            __float_as_uint(lo.w), __float_as_uint(hi.w),
                            __float_as_uint(bf[nt].z), __float_as_uint(bf[nt].w));
            }
        }
    }

    // epilogue: bias + store. One f_out per CTA column (BN == 256).
    const float bv = bias[blockIdx.y];
    #pragma unroll
    for (int mt = 0; mt < 4; ++mt) {
        const int r0 = m0 + wm * 64 + mt * 16 + g;
        #pragma unroll
        for (int nt = 0; nt < 4; ++nt) {
            const int c = n0 + wn * 32 + nt * 8 + tig * 2;
            float2 v0 = { acc[mt][nt][0] + bv, acc[mt][nt][1] + bv };
            float2 v1 = { acc[mt][nt][2] + bv, acc[mt][nt][3] + bv };
            *(float2*)(out + (size_t)r0 * NDIM + c)       = v0;
            *(float2*)(out + (size_t)(r0 + 8) * NDIM + c) = v1;
        }
    }
}

// ============================================================================
// Launch
// ============================================================================
extern "C" void kernel_launch(void* const* d_in, const int* in_sizes, int n_in,
                              void* d_out, int out_size) {
    const float* x    = (const float*)d_in[0];   // (2048, 32, 256)
    const float* kern = (const float*)d_in[1];   // (32, 32, 256)
    const float* bias = (const float*)d_in[2];   // (32,)
    const int*   pt   = (const int*)d_in[3];     // (256, 256)
    float* out = (float*)d_out;                  // (2048, 32, 256)

    cudaFuncSetAttribute(gemm_f16, cudaFuncAttributeMaxDynamicSharedMemorySize,
                         SMEM_TOTAL);

    convert_x_kernel<<<MDIM * (KDIM / 2) / 256, 256>>>(
        reinterpret_cast<const float2*>(x));
    transpose_pt_kernel<<<256, 256>>>(pt);
    expand_w_kernel<<<1024, 256>>>(kern);
    gemm_f16<<<dim3(MDIM / BM, NDIM / BN, 1), 512, SMEM_TOTAL>>>(bias, out);
}